// round 16
// baseline (speedup 1.0000x reference)
#include <cuda_runtime.h>
#include <cuda_bf16.h>
#include <cstdint>

#define B_   32
#define S_   512
#define E_   8
#define H_   768
#define KG_  100
#define MH_  1000
#define NROW 256
#define MHP  1024            /* padded hidden */
#define K1P  128             /* k1 K padded  */
#define KP1E 136             /* k1 smem pitch (elements) */
#define KPE2 136             /* k2 smem pitch (elements) */
#define K2BLK 384            /* k2 blocks inside kB */

// Scratch (device globals — no allocation allowed)
__device__ __align__(16) __nv_bfloat16 g_Xh[NROW * K1P];
__device__ __align__(16) __nv_bfloat16 g_Xl[NROW * K1P];
__device__ __align__(16) __nv_bfloat16 g_W1h[MHP * K1P];   // [n][k]
__device__ __align__(16) __nv_bfloat16 g_W1l[MHP * K1P];
__device__ __align__(16) __nv_bfloat16 g_W2h[H_ * MHP];    // [n][k]
__device__ __align__(16) __nv_bfloat16 g_W2l[H_ * MHP];
__device__ __align__(16) __nv_bfloat16 g_Hs_hi[NROW * MHP];
__device__ __align__(16) __nv_bfloat16 g_Hs_lo[NROW * MHP];
__device__ __align__(16) float g_ENT4[4][NROW * H_];
__device__ int g_prep;   // W1+X split blocks done (target 160)
__device__ int g_done;   // k2 blocks done (target K2BLK)

// ---------------- helpers ---------------------------------------------------
__device__ __forceinline__ uint32_t smem_u32(const void* p) {
    uint32_t a;
    asm("{ .reg .u64 t; cvta.to.shared.u64 t, %1; cvt.u32.u64 %0, t; }"
        : "=r"(a) : "l"(p));
    return a;
}
__device__ __forceinline__ int ld_acquire(const int* p) {
    int v;
    asm volatile("ld.acquire.gpu.b32 %0, [%1];" : "=r"(v) : "l"(p) : "memory");
    return v;
}
__device__ __forceinline__ void splitbf(float x, unsigned short& h,
                                        unsigned short& l) {
    __nv_bfloat16 hb = __float2bfloat16(x);
    float r = x - __bfloat162float(hb);
    __nv_bfloat16 lb = __float2bfloat16(r);
    h = *(unsigned short*)&hb;
    l = *(unsigned short*)&lb;
}
__device__ __forceinline__ void ldm_x4(uint32_t* r, uint32_t addr) {
    asm volatile("ldmatrix.sync.aligned.m8n8.x4.shared.b16 {%0,%1,%2,%3}, [%4];"
                 : "=r"(r[0]), "=r"(r[1]), "=r"(r[2]), "=r"(r[3]) : "r"(addr));
}
__device__ __forceinline__ void ldm_x2(uint32_t* r, uint32_t addr) {
    asm volatile("ldmatrix.sync.aligned.m8n8.x2.shared.b16 {%0,%1}, [%2];"
                 : "=r"(r[0]), "=r"(r[1]) : "r"(addr));
}
__device__ __forceinline__ void mma16816(float* c, const uint32_t* a,
                                         const uint32_t* b) {
    asm volatile(
        "mma.sync.aligned.m16n8k16.row.col.f32.bf16.bf16.f32 "
        "{%0,%1,%2,%3}, {%4,%5,%6,%7}, {%8,%9}, {%0,%1,%2,%3};"
        : "+f"(c[0]), "+f"(c[1]), "+f"(c[2]), "+f"(c[3])
        : "r"(a[0]), "r"(a[1]), "r"(a[2]), "r"(a[3]), "r"(b[0]), "r"(b[1]));
}

#define SM1_AL (32 * KP1E * 2)
#define SM1_BH (2 * SM1_AL)
#define SM1_BL (SM1_BH + 128 * KP1E * 2)
#define SMEM1  (SM1_BL + 128 * KP1E * 2)   /* 87040 */

#define SM2_AL (32 * KPE2 * 2)             /* 8704  */
#define SM2_BH (2 * SM2_AL)                /* 17408 */
#define SM2_BL (SM2_BH + 64 * KPE2 * 2)    /* 34816 */
#define SMEM2  (SM2_BL + 64 * KPE2 * 2)    /* 52224 */

// ---------------------------------------------------------------------------
// kA = kprep + k1 fused.  grid 992, block 256.
//   bid   0..127 : W1 split (releases g_prep)
//   bid 128..159 : X  split (releases g_prep)
//   bid 160..927 : W2 split
//   bid 928..991 : k1 HMMA (spins g_prep >= 160; scheduled last -> ~no spin)
// ---------------------------------------------------------------------------
__global__ void __launch_bounds__(256) kA(const float* __restrict__ W2,
                                          const float* __restrict__ W1,
                                          const float* __restrict__ X,
                                          const float* __restrict__ b1) {
    extern __shared__ char dsm[];
    __shared__ unsigned short sh[32][33], sl[32][33];
    const int bid = blockIdx.x;
    const int tid = threadIdx.x;
    const int tx = tid & 31, ty = tid >> 5;   // ty 0..7

    if (bid == 0 && tid == 0) g_done = 0;     // reset kB's counter (no kA reader)

    if (bid < 128) {
        // ---- W1 split: [k][n] -> g_W1h/l [n][k], 32x32 transpose tile ----
        const int t = bid;
        const int k0 = (t & 3) * 32, n0 = (t >> 2) * 32;
        #pragma unroll
        for (int j = 0; j < 4; j++) {
            int k = k0 + ty + j * 8;
            float v = (k < KG_ && (n0 + tx) < MH_) ? __ldg(W1 + k * MH_ + n0 + tx)
                                                   : 0.0f;
            unsigned short h, l; splitbf(v, h, l);
            sh[ty + j * 8][tx] = h; sl[ty + j * 8][tx] = l;
        }
        __syncthreads();
        #pragma unroll
        for (int j = 0; j < 4; j++) {
            int nn = ty + j * 8;
            g_W1h[(n0 + nn) * K1P + k0 + tx] = *(__nv_bfloat16*)&sh[tx][nn];
            g_W1l[(n0 + nn) * K1P + k0 + tx] = *(__nv_bfloat16*)&sl[tx][nn];
        }
        __threadfence();
        __syncthreads();
        if (tid == 0) atomicAdd(&g_prep, 1);
    } else if (bid < 160) {
        // ---- X split (no transpose) ----
        const int t = bid - 128;
        const int r0 = (t >> 2) * 32, k0 = (t & 3) * 32;
        #pragma unroll
        for (int j = 0; j < 4; j++) {
            int r = r0 + ty + j * 8, k = k0 + tx;
            float v = (k < KG_) ? __ldg(X + r * KG_ + k) : 0.0f;
            unsigned short h, l; splitbf(v, h, l);
            g_Xh[r * K1P + k] = *(__nv_bfloat16*)&h;
            g_Xl[r * K1P + k] = *(__nv_bfloat16*)&l;
        }
        __threadfence();
        __syncthreads();
        if (tid == 0) atomicAdd(&g_prep, 1);
    } else if (bid < 928) {
        // ---- W2 split: [k][n] -> g_W2h/l [n][k] ----
        const int t = bid - 160;
        const int k0 = (t & 31) * 32, n0 = (t >> 5) * 32;
        #pragma unroll
        for (int j = 0; j < 4; j++) {
            int k = k0 + ty + j * 8;
            float v = (k < MH_) ? __ldg(W2 + (long long)k * H_ + n0 + tx) : 0.0f;
            unsigned short h, l; splitbf(v, h, l);
            sh[ty + j * 8][tx] = h; sl[ty + j * 8][tx] = l;
        }
        __syncthreads();
        #pragma unroll
        for (int j = 0; j < 4; j++) {
            int nn = ty + j * 8;
            g_W2h[(n0 + nn) * MHP + k0 + tx] = *(__nv_bfloat16*)&sh[tx][nn];
            g_W2l[(n0 + nn) * MHP + k0 + tx] = *(__nv_bfloat16*)&sl[tx][nn];
        }
        // no counter: kB launches after kA completes (stream order)
    } else {
        // ---- k1 HMMA: Hs = relu(X @ W1 + b1) -> split hi/lo ----
        const int bidk = bid - 928;
        const int rb = (bidk & 7) * 32;
        const int n0 = (bidk >> 3) * 128;
        const uint32_t sb = smem_u32(dsm);
        const int lane = tid & 31, wid = tid >> 5;

        if (tid == 0) {
            while (ld_acquire(&g_prep) < 160) __nanosleep(64);
        }
        __syncthreads();

        // Stage A (hi/lo): 512 uint4 total
        for (int idx = tid; idx < 512; idx += 256) {
            int r = idx >> 4, c = idx & 15;
            uint4 vh = *(const uint4*)(g_Xh + (rb + r) * K1P + c * 8);
            uint4 vl = *(const uint4*)(g_Xl + (rb + r) * K1P + c * 8);
            *(uint4*)(dsm + (r * KP1E + c * 8) * 2)          = vh;
            *(uint4*)(dsm + SM1_AL + (r * KP1E + c * 8) * 2) = vl;
        }
        // Stage B (hi/lo): 2048 uint4 total
        for (int idx = tid; idx < 2048; idx += 256) {
            int n = idx >> 4, c = idx & 15;
            uint4 vh = *(const uint4*)(g_W1h + (n0 + n) * K1P + c * 8);
            uint4 vl = *(const uint4*)(g_W1l + (n0 + n) * K1P + c * 8);
            *(uint4*)(dsm + SM1_BH + (n * KP1E + c * 8) * 2) = vh;
            *(uint4*)(dsm + SM1_BL + (n * KP1E + c * 8) * 2) = vl;
        }
        __syncthreads();

        if (wid < 4) {
            const int n_w = wid * 32;
            float acc[2][4][4];
            #pragma unroll
            for (int i = 0; i < 2; i++)
                #pragma unroll
                for (int j = 0; j < 4; j++)
                    #pragma unroll
                    for (int q = 0; q < 4; q++) acc[i][j][q] = 0.0f;

            const uint32_t arow = lane & 15;
            const uint32_t akof = (lane >> 4) << 3;
            const uint32_t brow = lane & 7;
            const uint32_t bkof = ((lane >> 3) & 1) << 3;

            #pragma unroll
            for (int ks = 0; ks < 8; ks++) {
                const uint32_t kk = ks * 16;
                uint32_t ah[2][4], al[2][4], bh[4][2], bl[4][2];
                #pragma unroll
                for (int i = 0; i < 2; i++) {
                    uint32_t ro = (i * 16 + arow) * KP1E + kk + akof;
                    ldm_x4(ah[i], sb + ro * 2);
                    ldm_x4(al[i], sb + SM1_AL + ro * 2);
                }
                #pragma unroll
                for (int j = 0; j < 4; j++) {
                    uint32_t ro = (n_w + j * 8 + brow) * KP1E + kk + bkof;
                    ldm_x2(bh[j], sb + SM1_BH + ro * 2);
                    ldm_x2(bl[j], sb + SM1_BL + ro * 2);
                }
                #pragma unroll
                for (int i = 0; i < 2; i++)
                    #pragma unroll
                    for (int j = 0; j < 4; j++) {
                        mma16816(acc[i][j], ah[i], bh[j]);
                        mma16816(acc[i][j], ah[i], bl[j]);
                        mma16816(acc[i][j], al[i], bh[j]);
                    }
            }

            #pragma unroll
            for (int i = 0; i < 2; i++) {
                int row = rb + i * 16 + (lane >> 2);
                #pragma unroll
                for (int j = 0; j < 4; j++) {
                    int col = n0 + n_w + j * 8 + (lane & 3) * 2;
                    float bb0 = (col     < MH_) ? __ldg(b1 + col)     : 0.0f;
                    float bb1 = (col + 1 < MH_) ? __ldg(b1 + col + 1) : 0.0f;
                    float f0 = fmaxf(acc[i][j][0] + bb0, 0.0f);
                    float f1 = fmaxf(acc[i][j][1] + bb1, 0.0f);
                    float f2 = fmaxf(acc[i][j][2] + bb0, 0.0f);
                    float f3 = fmaxf(acc[i][j][3] + bb1, 0.0f);
                    if (col >= MH_) f0 = f1 = f2 = f3 = 0.0f;
                    unsigned short h0, l0, h1, l1;
                    splitbf(f0, h0, l0); splitbf(f1, h1, l1);
                    *(uint32_t*)(g_Hs_hi + row * MHP + col) = (uint32_t)h0 | ((uint32_t)h1 << 16);
                    *(uint32_t*)(g_Hs_lo + row * MHP + col) = (uint32_t)l0 | ((uint32_t)l1 << 16);
                    splitbf(f2, h0, l0); splitbf(f3, h1, l1);
                    *(uint32_t*)(g_Hs_hi + (row + 8) * MHP + col) = (uint32_t)h0 | ((uint32_t)h1 << 16);
                    *(uint32_t*)(g_Hs_lo + (row + 8) * MHP + col) = (uint32_t)l0 | ((uint32_t)l1 << 16);
                }
            }
        }
    }
}

// ---------------------------------------------------------------------------
// kB = k2 + k3 fused.  grid 4480, block 192.
//   bid 0..383   : k2 HMMA (128 active threads) -> g_ENT4; releases g_done
//   bid 384..4479: k3 gather (+ flagged warps spin on g_done, add entities)
// All k2 blocks fit in wave 1 (4 blocks/SM x 148 = 592 >= 384, bid order),
// so k3's gathers overlap k2's compute; unflagged k3 blocks never wait.
// ---------------------------------------------------------------------------
__global__ void __launch_bounds__(192) kB(const int*   __restrict__ ids,
                                          const float* __restrict__ mask,
                                          const float* __restrict__ we,
                                          const float* __restrict__ b2,
                                          float*       __restrict__ out) {
    extern __shared__ char dsm[];
    const int bid = blockIdx.x;
    const int tid = threadIdx.x;
    const int lane = tid & 31;

    if (bid < K2BLK) {
        // ================= k2 =================
        if (bid == 0 && tid == 0) g_prep = 0;   // reset kA's counter
        const uint32_t sb = smem_u32(dsm);
        const int wid = tid >> 5;               // 0..5; compute on wid<4
        const int rb = (bid & 7) * 32;
        const int by = (bid >> 3) % 12;
        const int kz = bid / 96;
        const int n0 = by * 64;
        const int n_w = (wid & 3) * 16;

        float acc[2][2][4];
        #pragma unroll
        for (int i = 0; i < 2; i++)
            #pragma unroll
            for (int j = 0; j < 2; j++)
                #pragma unroll
                for (int q = 0; q < 4; q++) acc[i][j][q] = 0.0f;

        const uint32_t arow = lane & 15;
        const uint32_t akof = (lane >> 4) << 3;
        const uint32_t brow = lane & 7;
        const uint32_t bkof = ((lane >> 3) & 1) << 3;

        #pragma unroll
        for (int ch = 0; ch < 2; ch++) {
            const int kb = kz * 256 + ch * 128;
            if (ch) __syncthreads();

            for (int idx = tid; idx < 512; idx += 192) {      // A: 32x16 uint4
                int r = idx >> 4, c = idx & 15;
                uint4 vh = *(const uint4*)(g_Hs_hi + (rb + r) * MHP + kb + c * 8);
                uint4 vl = *(const uint4*)(g_Hs_lo + (rb + r) * MHP + kb + c * 8);
                *(uint4*)(dsm + (r * KPE2 + c * 8) * 2)          = vh;
                *(uint4*)(dsm + SM2_AL + (r * KPE2 + c * 8) * 2) = vl;
            }
            for (int idx = tid; idx < 1024; idx += 192) {     // B: 64x16 uint4
                int n = idx >> 4, c = idx & 15;
                uint4 vh = *(const uint4*)(g_W2h + (n0 + n) * MHP + kb + c * 8);
                uint4 vl = *(const uint4*)(g_W2l + (n0 + n) * MHP + kb + c * 8);
                *(uint4*)(dsm + SM2_BH + (n * KPE2 + c * 8) * 2) = vh;
                *(uint4*)(dsm + SM2_BL + (n * KPE2 + c * 8) * 2) = vl;
            }
            __syncthreads();

            if (wid < 4) {
                #pragma unroll
                for (int ks = 0; ks < 8; ks++) {
                    const uint32_t kk = ks * 16;
                    uint32_t ah[2][4], al[2][4], bh[2][2], bl[2][2];
                    #pragma unroll
                    for (int i = 0; i < 2; i++) {
                        uint32_t ro = (i * 16 + arow) * KPE2 + kk + akof;
                        ldm_x4(ah[i], sb + ro * 2);
                        ldm_x4(al[i], sb + SM2_AL + ro * 2);
                    }
                    #pragma unroll
                    for (int j = 0; j < 2; j++) {
                        uint32_t ro = (n_w + j * 8 + brow) * KPE2 + kk + bkof;
                        ldm_x2(bh[j], sb + SM2_BH + ro * 2);
                        ldm_x2(bl[j], sb + SM2_BL + ro * 2);
                    }
                    #pragma unroll
                    for (int i = 0; i < 2; i++)
                        #pragma unroll
                        for (int j = 0; j < 2; j++) {
                            mma16816(acc[i][j], ah[i], bh[j]);
                            mma16816(acc[i][j], ah[i], bl[j]);
                            mma16816(acc[i][j], al[i], bh[j]);
                        }
                }
            }
        }

        if (wid < 4) {
            float* dst = g_ENT4[kz];
            #pragma unroll
            for (int i = 0; i < 2; i++) {
                int row = rb + i * 16 + (lane >> 2);
                #pragma unroll
                for (int j = 0; j < 2; j++) {
                    int col = n0 + n_w + j * 8 + (lane & 3) * 2;
                    float bb0 = 0.f, bb1 = 0.f;
                    if (kz == 0) { bb0 = __ldg(b2 + col); bb1 = __ldg(b2 + col + 1); }
                    float2 o0 = make_float2(acc[i][j][0] + bb0, acc[i][j][1] + bb1);
                    float2 o1 = make_float2(acc[i][j][2] + bb0, acc[i][j][3] + bb1);
                    *(float2*)(dst + row * H_ + col)       = o0;
                    *(float2*)(dst + (row + 8) * H_ + col) = o1;
                }
            }
        }
        __threadfence();
        __syncthreads();
        if (tid == 0) atomicAdd(&g_done, 1);
    } else {
        // ================= k3 =================
        const int rblk = bid - K2BLK;             // 0..4095
        const int b    = rblk >> 7;
        const int s0   = (rblk & 127) << 2;
        const int row0 = b * S_ + s0;

        int wid0 = __ldg(ids + row0 + 0);
        int wid1 = __ldg(ids + row0 + 1);
        int wid2 = __ldg(ids + row0 + 2);
        int wid3 = __ldg(ids + row0 + 3);

        const float4* __restrict__ we4 = (const float4*)we;
        float4 v0 = we4[(long long)wid0 * (H_ / 4) + tid];
        float4 v1 = we4[(long long)wid1 * (H_ / 4) + tid];
        float4 v2 = we4[(long long)wid2 * (H_ / 4) + tid];
        float4 v3 = we4[(long long)wid3 * (H_ / 4) + tid];

        const float mval = __ldg(mask + (b * E_ + (lane >> 2)) * S_ + s0 + (lane & 3));
        const unsigned flag = __ballot_sync(0xffffffffu, mval != 0.0f);

        if (flag) {
            // Wait for all k2 blocks (acquire), gathers already in flight.
            while (ld_acquire(&g_done) < K2BLK) __nanosleep(128);

            #pragma unroll
            for (int e = 0; e < E_; e++) {
                const unsigned f4 = (flag >> (e * 4)) & 0xFu;
                if (f4) {
                    const int idx = (b * E_ + e) * (H_ / 4) + tid;
                    float4 p  = ((const float4*)g_ENT4[0])[idx];
                    float4 p1 = ((const float4*)g_ENT4[1])[idx];
                    float4 p2 = ((const float4*)g_ENT4[2])[idx];
                    float4 p3 = ((const float4*)g_ENT4[3])[idx];
                    p.x += p1.x + p2.x + p3.x;
                    p.y += p1.y + p2.y + p3.y;
                    p.z += p1.z + p2.z + p3.z;
                    p.w += p1.w + p2.w + p3.w;
                    const float m0 = __shfl_sync(0xffffffffu, mval, e * 4 + 0);
                    const float m1 = __shfl_sync(0xffffffffu, mval, e * 4 + 1);
                    const float m2 = __shfl_sync(0xffffffffu, mval, e * 4 + 2);
                    const float m3 = __shfl_sync(0xffffffffu, mval, e * 4 + 3);
                    if (f4 & 1u) {
                        v0.x = fmaf(m0, p.x, v0.x); v0.y = fmaf(m0, p.y, v0.y);
                        v0.z = fmaf(m0, p.z, v0.z); v0.w = fmaf(m0, p.w, v0.w); }
                    if (f4 & 2u) {
                        v1.x = fmaf(m1, p.x, v1.x); v1.y = fmaf(m1, p.y, v1.y);
                        v1.z = fmaf(m1, p.z, v1.z); v1.w = fmaf(m1, p.w, v1.w); }
                    if (f4 & 4u) {
                        v2.x = fmaf(m2, p.x, v2.x); v2.y = fmaf(m2, p.y, v2.y);
                        v2.z = fmaf(m2, p.z, v2.z); v2.w = fmaf(m2, p.w, v2.w); }
                    if (f4 & 8u) {
                        v3.x = fmaf(m3, p.x, v3.x); v3.y = fmaf(m3, p.y, v3.y);
                        v3.z = fmaf(m3, p.z, v3.z); v3.w = fmaf(m3, p.w, v3.w); }
                }
            }
        }

        float4* __restrict__ out4 = (float4*)out;
        __stcs(out4 + (long long)(row0 + 0) * (H_ / 4) + tid, v0);
        __stcs(out4 + (long long)(row0 + 1) * (H_ / 4) + tid, v1);
        __stcs(out4 + (long long)(row0 + 2) * (H_ / 4) + tid, v2);
        __stcs(out4 + (long long)(row0 + 3) * (H_ / 4) + tid, v3);
    }
}

// ---------------------------------------------------------------------------
extern "C" void kernel_launch(void* const* d_in, const int* in_sizes, int n_in,
                              void* d_out, int out_size) {
    const int*   ids  = (const int*)  d_in[0];
    const float* X    = (const float*)d_in[1];
    const float* msk  = (const float*)d_in[2];
    const float* we   = (const float*)d_in[3];
    const float* W1   = (const float*)d_in[4];
    const float* b1   = (const float*)d_in[5];
    const float* W2   = (const float*)d_in[6];
    const float* b2   = (const float*)d_in[7];
    float* out = (float*)d_out;

    cudaFuncSetAttribute(kA, cudaFuncAttributeMaxDynamicSharedMemorySize, SMEM1);
    cudaFuncSetAttribute(kB, cudaFuncAttributeMaxDynamicSharedMemorySize, SMEM2);

    kA<<<992, 256, SMEM1>>>(W2, W1, X, b1);
    kB<<<K2BLK + 4096, 192, SMEM2>>>(ids, msk, we, b2, out);
}